// round 3
// baseline (speedup 1.0000x reference)
#include <cuda_runtime.h>
#include <cuda_bf16.h>

#define BS   128
#define OBJ  512
#define RNN  1024
#define HID  512
#define KCHUNKS 32   // k-chunks of 32

// GEMM partials: [kchunk][b][hid] (8MB, L2-resident). Summed with bias in
// scores kernel -> deterministic, no atomics, no init kernel.
__device__ float g_part[KCHUNKS * BS * HID];
// Score scratch: [b][obj]
__device__ float g_scores[BS * OBJ];

__device__ __forceinline__ float tanh_fast(float x) {
    float y;
    asm("tanh.approx.f32 %0, %1;" : "=f"(y) : "f"(x));
    return y;
}

// ---------------- GEMM: att_h partials ----------------
// grid (16 n-tiles of 32, 32 k-chunks of 32), 256 threads, single stage:
// one front-batched LDG round (MLP=5/thread), one sync, 32 FMA iters.
// ~3.5 blocks/SM resident. out_part[b][n] = sum_{k in chunk} h[b][k]*W[n][k]
__global__ __launch_bounds__(256) void gemm_kernel(
    const float* __restrict__ h, const float* __restrict__ W)
{
    __shared__ float h_s[32][129];   // [k][b], padded
    __shared__ float w_s[32][33];    // [k][j], padded
    const int n0 = blockIdx.x * 32;
    const int k0 = blockIdx.y * 32;
    const int t  = threadIdx.x;
    const int tm = t & 31;    // rows tm, +32, +64, +96
    const int tn = t >> 5;    // cols tn, +8, +16, +24

    // Front-batch all 5 global loads into registers
    float4 hv[4], wv;
    int hb[4], hk[4];
    #pragma unroll
    for (int r = 0; r < 4; ++r) {
        int f = t + 256 * r;
        hb[r] = f >> 3;           // 8 float4 per b-row
        hk[r] = f & 7;
        hv[r] = *(const float4*)(h + hb[r] * RNN + k0 + hk[r] * 4);
    }
    const int wj = t >> 3, wk = t & 7;
    wv = *(const float4*)(W + (n0 + wj) * RNN + k0 + wk * 4);

    #pragma unroll
    for (int r = 0; r < 4; ++r) {
        h_s[hk[r]*4+0][hb[r]] = hv[r].x; h_s[hk[r]*4+1][hb[r]] = hv[r].y;
        h_s[hk[r]*4+2][hb[r]] = hv[r].z; h_s[hk[r]*4+3][hb[r]] = hv[r].w;
    }
    w_s[wk*4+0][wj] = wv.x; w_s[wk*4+1][wj] = wv.y;
    w_s[wk*4+2][wj] = wv.z; w_s[wk*4+3][wj] = wv.w;
    __syncthreads();

    float acc[4][4] = {};
    #pragma unroll 8
    for (int k = 0; k < 32; ++k) {
        float a0 = h_s[k][tm],      a1 = h_s[k][tm + 32],
              a2 = h_s[k][tm + 64], a3 = h_s[k][tm + 96];
        float b0 = w_s[k][tn],      b1 = w_s[k][tn + 8],
              b2 = w_s[k][tn + 16], b3 = w_s[k][tn + 24];
        acc[0][0] += a0*b0; acc[0][1] += a0*b1; acc[0][2] += a0*b2; acc[0][3] += a0*b3;
        acc[1][0] += a1*b0; acc[1][1] += a1*b1; acc[1][2] += a1*b2; acc[1][3] += a1*b3;
        acc[2][0] += a2*b0; acc[2][1] += a2*b1; acc[2][2] += a2*b2; acc[2][3] += a2*b3;
        acc[3][0] += a3*b0; acc[3][1] += a3*b1; acc[3][2] += a3*b2; acc[3][3] += a3*b3;
    }

    float* outp = g_part + blockIdx.y * (BS * HID);
    #pragma unroll
    for (int i = 0; i < 4; ++i)
        #pragma unroll
        for (int j = 0; j < 4; ++j)
            outp[(tm + 32*i) * HID + n0 + tn + 8*j] = acc[i][j];
}

// ---------------- Scores: tanh + rank-1 dot ----------------
// grid 512 (= 128 b x 4 obj-chunks of 128), 256 threads. Streams att_feats
// with __ldcs; o-loop unrolled x2 with front-batched loads (MLP=8/warp).
// b_alpha dropped (cancels in softmax).
__global__ __launch_bounds__(256) void scores_kernel(
    const float* __restrict__ att_feats,
    const float* __restrict__ b_h2att,
    const float* __restrict__ w_alpha)
{
    const int b     = blockIdx.x >> 2;
    const int chunk = blockIdx.x & 3;
    __shared__ float ah[HID];
    __shared__ float wa[HID];
    const int t = threadIdx.x;

    #pragma unroll
    for (int e = 0; e < 2; ++e) {
        int idx = t + 256 * e;
        float s = b_h2att[idx];
        #pragma unroll 8
        for (int c = 0; c < KCHUNKS; ++c)
            s += g_part[c * (BS * HID) + b * HID + idx];
        ah[idx] = s;
        wa[idx] = w_alpha[idx];
    }
    __syncthreads();

    const int w = t >> 5, lane = t & 31;
    const float4* base = (const float4*)(att_feats
                         + (size_t)b * OBJ * HID + (size_t)chunk * 128 * HID);
    const float4* ah4  = (const float4*)ah;
    const float4* wa4  = (const float4*)wa;

    // 128 objects / 8 warps = 16 per warp, processed 2 per iteration.
    for (int o = w; o < 128; o += 16) {
        const float4* r0 = base + o        * (HID / 4);
        const float4* r1 = base + (o + 8)  * (HID / 4);
        float4 f0[4], f1[4];
        #pragma unroll
        for (int i = 0; i < 4; ++i) {
            f0[i] = __ldcs(r0 + lane + 32 * i);
            f1[i] = __ldcs(r1 + lane + 32 * i);
        }
        float s0 = 0.f, s1 = 0.f;
        #pragma unroll
        for (int i = 0; i < 4; ++i) {
            int idx = lane + 32 * i;
            float4 a  = ah4[idx];
            float4 wv = wa4[idx];
            s0 += tanh_fast(f0[i].x + a.x) * wv.x;
            s0 += tanh_fast(f0[i].y + a.y) * wv.y;
            s0 += tanh_fast(f0[i].z + a.z) * wv.z;
            s0 += tanh_fast(f0[i].w + a.w) * wv.w;
            s1 += tanh_fast(f1[i].x + a.x) * wv.x;
            s1 += tanh_fast(f1[i].y + a.y) * wv.y;
            s1 += tanh_fast(f1[i].z + a.z) * wv.z;
            s1 += tanh_fast(f1[i].w + a.w) * wv.w;
        }
        #pragma unroll
        for (int d = 16; d; d >>= 1) {
            s0 += __shfl_xor_sync(0xffffffffu, s0, d);
            s1 += __shfl_xor_sync(0xffffffffu, s1, d);
        }
        if (lane == 0) {
            g_scores[b * OBJ + chunk * 128 + o]     = s0;
            g_scores[b * OBJ + chunk * 128 + o + 8] = s1;
        }
    }
}

// ---------------- Masked softmax ----------------
// grid 128, 512 threads. softmax->mask->renorm collapses to masked softmax.
__global__ __launch_bounds__(512) void softmax_kernel(
    const int* __restrict__ att_masks, float* __restrict__ out)
{
    const int b = blockIdx.x;
    const int t = threadIdx.x;
    const int w = t >> 5, lane = t & 31;
    __shared__ float red[16];

    float sc = g_scores[b * OBJ + t];

    float v = sc;
    #pragma unroll
    for (int d = 16; d; d >>= 1) v = fmaxf(v, __shfl_xor_sync(0xffffffffu, v, d));
    if (lane == 0) red[w] = v;
    __syncthreads();
    if (w == 0) {
        float m = red[lane & 15];
        #pragma unroll
        for (int d = 8; d; d >>= 1) m = fmaxf(m, __shfl_xor_sync(0xffffffffu, m, d));
        if (lane == 0) red[0] = m;
    }
    __syncthreads();
    const float mx = red[0];

    float m = (float)att_masks[b * OBJ + t];
    float e = m * __expf(sc - mx);
    float s = e;
    #pragma unroll
    for (int d = 16; d; d >>= 1) s += __shfl_xor_sync(0xffffffffu, s, d);
    __syncthreads();
    if (lane == 0) red[w] = s;
    __syncthreads();
    if (w == 0) {
        float z = red[lane & 15];
        #pragma unroll
        for (int d = 8; d; d >>= 1) z += __shfl_xor_sync(0xffffffffu, z, d);
        if (lane == 0) red[0] = z;
    }
    __syncthreads();
    out[b * OBJ + t] = e * (1.f / red[0]);
}

extern "C" void kernel_launch(void* const* d_in, const int* in_sizes, int n_in,
                              void* d_out, int out_size) {
    const float* h         = (const float*)d_in[0];
    const float* att_feats = (const float*)d_in[1];
    const int*   att_masks = (const int*)  d_in[2];
    const float* W_h2att   = (const float*)d_in[3];
    const float* b_h2att   = (const float*)d_in[4];
    const float* w_alpha   = (const float*)d_in[5];
    // d_in[6] = b_alpha: cancels in softmax, unused.
    float* out = (float*)d_out;

    gemm_kernel<<<dim3(16, 32), 256>>>(h, W_h2att);
    scores_kernel<<<512, 256>>>(att_feats, b_h2att, w_alpha);
    softmax_kernel<<<BS, 512>>>(att_masks, out);
}

// round 4
// speedup vs baseline: 1.2740x; 1.2740x over previous
#include <cuda_runtime.h>
#include <cuda_bf16.h>

#define BS   128
#define OBJ  512
#define RNN  1024
#define HID  512
#define KCHUNKS 16   // k-chunks of 64

// GEMM partials, TRANSPOSED layout [chunk][hid][bs] so GEMM stores are
// coalesced (lanes vary over b). 4MB, L2-resident.
__device__ float g_part[KCHUNKS * HID * BS];
// Reduced att_h + bias, layout [hid][bs] (256KB, L2-resident).
__device__ float g_atth[HID * BS];
// Score scratch: [b][obj]
__device__ float g_scores[BS * OBJ];

__device__ __forceinline__ float tanh_fast(float x) {
    float y;
    asm("tanh.approx.f32 %0, %1;" : "=f"(y) : "f"(x));
    return y;
}

// ---------------- GEMM: att_h partials ----------------
// grid (16 n-tiles of 32, 16 k-chunks of 64), 256 threads. Two k-stages of
// 32, software pipelined (stage-2 LDGs issued before stage-1 compute).
// part[c][n][b] = sum_{k in chunk c} h[b][k] * W[n][k]; stores coalesced.
__global__ __launch_bounds__(256) void gemm_kernel(
    const float* __restrict__ h, const float* __restrict__ W)
{
    __shared__ float h_s[32][129];   // [k][b], padded
    __shared__ float w_s[32][33];    // [k][j], padded
    const int n0 = blockIdx.x * 32;
    const int k0 = blockIdx.y * 64;
    const int t  = threadIdx.x;
    const int tm = t & 31;    // b rows tm, +32, +64, +96
    const int tn = t >> 5;    // n cols tn, +8, +16, +24

    const int hb = t >> 3, hk = t & 7;        // h: 4 rows per thread-slot
    const int wj = t >> 3, wk = t & 7;

    // ---- stage 1 loads (kk = 0) ----
    float4 hv[4], wv;
    #pragma unroll
    for (int r = 0; r < 4; ++r)
        hv[r] = *(const float4*)(h + (hb + 32 * r) * RNN + k0 + hk * 4);
    wv = *(const float4*)(W + (n0 + wj) * RNN + k0 + wk * 4);

    #pragma unroll
    for (int r = 0; r < 4; ++r) {
        h_s[hk*4+0][hb + 32*r] = hv[r].x; h_s[hk*4+1][hb + 32*r] = hv[r].y;
        h_s[hk*4+2][hb + 32*r] = hv[r].z; h_s[hk*4+3][hb + 32*r] = hv[r].w;
    }
    w_s[wk*4+0][wj] = wv.x; w_s[wk*4+1][wj] = wv.y;
    w_s[wk*4+2][wj] = wv.z; w_s[wk*4+3][wj] = wv.w;
    __syncthreads();

    // ---- stage 2 loads issued now, consumed after stage-1 compute ----
    float4 hv2[4], wv2;
    #pragma unroll
    for (int r = 0; r < 4; ++r)
        hv2[r] = *(const float4*)(h + (hb + 32 * r) * RNN + k0 + 32 + hk * 4);
    wv2 = *(const float4*)(W + (n0 + wj) * RNN + k0 + 32 + wk * 4);

    float acc[4][4] = {};
    #pragma unroll 8
    for (int k = 0; k < 32; ++k) {
        float a0 = h_s[k][tm],      a1 = h_s[k][tm + 32],
              a2 = h_s[k][tm + 64], a3 = h_s[k][tm + 96];
        float b0 = w_s[k][tn],      b1 = w_s[k][tn + 8],
              b2 = w_s[k][tn + 16], b3 = w_s[k][tn + 24];
        acc[0][0] += a0*b0; acc[0][1] += a0*b1; acc[0][2] += a0*b2; acc[0][3] += a0*b3;
        acc[1][0] += a1*b0; acc[1][1] += a1*b1; acc[1][2] += a1*b2; acc[1][3] += a1*b3;
        acc[2][0] += a2*b0; acc[2][1] += a2*b1; acc[2][2] += a2*b2; acc[2][3] += a2*b3;
        acc[3][0] += a3*b0; acc[3][1] += a3*b1; acc[3][2] += a3*b2; acc[3][3] += a3*b3;
    }
    __syncthreads();

    #pragma unroll
    for (int r = 0; r < 4; ++r) {
        h_s[hk*4+0][hb + 32*r] = hv2[r].x; h_s[hk*4+1][hb + 32*r] = hv2[r].y;
        h_s[hk*4+2][hb + 32*r] = hv2[r].z; h_s[hk*4+3][hb + 32*r] = hv2[r].w;
    }
    w_s[wk*4+0][wj] = wv2.x; w_s[wk*4+1][wj] = wv2.y;
    w_s[wk*4+2][wj] = wv2.z; w_s[wk*4+3][wj] = wv2.w;
    __syncthreads();

    #pragma unroll 8
    for (int k = 0; k < 32; ++k) {
        float a0 = h_s[k][tm],      a1 = h_s[k][tm + 32],
              a2 = h_s[k][tm + 64], a3 = h_s[k][tm + 96];
        float b0 = w_s[k][tn],      b1 = w_s[k][tn + 8],
              b2 = w_s[k][tn + 16], b3 = w_s[k][tn + 24];
        acc[0][0] += a0*b0; acc[0][1] += a0*b1; acc[0][2] += a0*b2; acc[0][3] += a0*b3;
        acc[1][0] += a1*b0; acc[1][1] += a1*b1; acc[1][2] += a1*b2; acc[1][3] += a1*b3;
        acc[2][0] += a2*b0; acc[2][1] += a2*b1; acc[2][2] += a2*b2; acc[2][3] += a2*b3;
        acc[3][0] += a3*b0; acc[3][1] += a3*b1; acc[3][2] += a3*b2; acc[3][3] += a3*b3;
    }

    // Coalesced epilogue: lanes (tm) map to consecutive b.
    float* outp = g_part + blockIdx.y * (HID * BS);
    #pragma unroll
    for (int j = 0; j < 4; ++j)
        #pragma unroll
        for (int i = 0; i < 4; ++i)
            outp[(n0 + tn + 8*j) * BS + tm + 32*i] = acc[i][j];
}

// ---------------- Reduce: sum partials + bias ----------------
// grid 256 x 256 threads; one (n,b) element per thread. Fully coalesced.
__global__ __launch_bounds__(256) void reduce_kernel(
    const float* __restrict__ b_h2att)
{
    const int tid = blockIdx.x * 256 + threadIdx.x;   // n*BS + b
    float s = b_h2att[tid >> 7];   // warp-uniform (128 consecutive share n)
    #pragma unroll
    for (int c = 0; c < KCHUNKS; ++c)
        s += g_part[c * (HID * BS) + tid];
    g_atth[tid] = s;
}

// ---------------- Scores: tanh + rank-1 dot ----------------
// grid 512 (= 128 b x 4 obj-chunks of 128), 256 threads. Streams att_feats
// with __ldcs, MLP=8 per warp. b_alpha dropped (cancels in softmax).
__global__ __launch_bounds__(256) void scores_kernel(
    const float* __restrict__ att_feats,
    const float* __restrict__ w_alpha)
{
    const int b     = blockIdx.x >> 2;
    const int chunk = blockIdx.x & 3;
    __shared__ float ah[HID];
    __shared__ float wa[HID];
    const int t = threadIdx.x;

    #pragma unroll
    for (int e = 0; e < 2; ++e) {
        int idx = t + 256 * e;
        ah[idx] = g_atth[idx * BS + b];   // L2-resident, 2KB total
        wa[idx] = w_alpha[idx];
    }
    __syncthreads();

    const int w = t >> 5, lane = t & 31;
    const float4* base = (const float4*)(att_feats
                         + (size_t)b * OBJ * HID + (size_t)chunk * 128 * HID);
    const float4* ah4  = (const float4*)ah;
    const float4* wa4  = (const float4*)wa;

    // 128 objects / 8 warps = 16 per warp, 2 per iteration (8 LDG in flight).
    for (int o = w; o < 128; o += 16) {
        const float4* r0 = base + o       * (HID / 4);
        const float4* r1 = base + (o + 8) * (HID / 4);
        float4 f0[4], f1[4];
        #pragma unroll
        for (int i = 0; i < 4; ++i) {
            f0[i] = __ldcs(r0 + lane + 32 * i);
            f1[i] = __ldcs(r1 + lane + 32 * i);
        }
        float s0 = 0.f, s1 = 0.f;
        #pragma unroll
        for (int i = 0; i < 4; ++i) {
            int idx = lane + 32 * i;
            float4 a  = ah4[idx];
            float4 wv = wa4[idx];
            s0 += tanh_fast(f0[i].x + a.x) * wv.x;
            s0 += tanh_fast(f0[i].y + a.y) * wv.y;
            s0 += tanh_fast(f0[i].z + a.z) * wv.z;
            s0 += tanh_fast(f0[i].w + a.w) * wv.w;
            s1 += tanh_fast(f1[i].x + a.x) * wv.x;
            s1 += tanh_fast(f1[i].y + a.y) * wv.y;
            s1 += tanh_fast(f1[i].z + a.z) * wv.z;
            s1 += tanh_fast(f1[i].w + a.w) * wv.w;
        }
        #pragma unroll
        for (int d = 16; d; d >>= 1) {
            s0 += __shfl_xor_sync(0xffffffffu, s0, d);
            s1 += __shfl_xor_sync(0xffffffffu, s1, d);
        }
        if (lane == 0) {
            g_scores[b * OBJ + chunk * 128 + o]     = s0;
            g_scores[b * OBJ + chunk * 128 + o + 8] = s1;
        }
    }
}

// ---------------- Masked softmax ----------------
// grid 128, 512 threads. softmax->mask->renorm collapses to masked softmax.
__global__ __launch_bounds__(512) void softmax_kernel(
    const int* __restrict__ att_masks, float* __restrict__ out)
{
    const int b = blockIdx.x;
    const int t = threadIdx.x;
    const int w = t >> 5, lane = t & 31;
    __shared__ float red[16];

    float sc = g_scores[b * OBJ + t];

    float v = sc;
    #pragma unroll
    for (int d = 16; d; d >>= 1) v = fmaxf(v, __shfl_xor_sync(0xffffffffu, v, d));
    if (lane == 0) red[w] = v;
    __syncthreads();
    if (w == 0) {
        float m = red[lane & 15];
        #pragma unroll
        for (int d = 8; d; d >>= 1) m = fmaxf(m, __shfl_xor_sync(0xffffffffu, m, d));
        if (lane == 0) red[0] = m;
    }
    __syncthreads();
    const float mx = red[0];

    float m = (float)att_masks[b * OBJ + t];
    float e = m * __expf(sc - mx);
    float s = e;
    #pragma unroll
    for (int d = 16; d; d >>= 1) s += __shfl_xor_sync(0xffffffffu, s, d);
    __syncthreads();
    if (lane == 0) red[w] = s;
    __syncthreads();
    if (w == 0) {
        float z = red[lane & 15];
        #pragma unroll
        for (int d = 8; d; d >>= 1) z += __shfl_xor_sync(0xffffffffu, z, d);
        if (lane == 0) red[0] = z;
    }
    __syncthreads();
    out[b * OBJ + t] = e * (1.f / red[0]);
}

extern "C" void kernel_launch(void* const* d_in, const int* in_sizes, int n_in,
                              void* d_out, int out_size) {
    const float* h         = (const float*)d_in[0];
    const float* att_feats = (const float*)d_in[1];
    const int*   att_masks = (const int*)  d_in[2];
    const float* W_h2att   = (const float*)d_in[3];
    const float* b_h2att   = (const float*)d_in[4];
    const float* w_alpha   = (const float*)d_in[5];
    // d_in[6] = b_alpha: cancels in softmax, unused.
    float* out = (float*)d_out;

    gemm_kernel<<<dim3(16, 16), 256>>>(h, W_h2att);
    reduce_kernel<<<256, 256>>>(b_h2att);
    scores_kernel<<<512, 256>>>(att_feats, w_alpha);
    softmax_kernel<<<BS, 512>>>(att_masks, out);
}